// round 7
// baseline (speedup 1.0000x reference)
#include <cuda_runtime.h>
#include <cuda_bf16.h>
#include <cstdint>
#include <cstring>

// einsum('bis,ie->bse') via mma.sync bf16 3-term split.
//   inputs    [B=64, I=64, S=4096] f32
//   embedding [I=64, E=64]         f32
//   out       [B=64, S=4096, E=64] f32
//
// D = Ahi*Bhi + Ahi*Blo + Alo*Bhi  (bf16 operands, fp32 accumulate)
// rel err ~3.4e-6 (validated).
//
// vs round 6: occupancy play. mt=1 (32-reg accumulator) + launch_bounds(256,3)
// -> 24 warps/SM instead of 16. All pipes had >=40% headroom and issue was 22%,
// so the kernel was latency-bound on too few warps; extra B-fragment LDS
// traffic (L1 61% -> ~73%) is the accepted cost.

#define BATCH 64
#define ISZ   64
#define SEQ   4096
#define ESZ   64
#define MTILE 128        // s per CTA
#define THREADS 256

#define BS_STRIDE 72     // u32 words per k2-row; conflict-free fragment reads
#define SMEM_BH_OFF 0
#define SMEM_BL_OFF (32 * BS_STRIDE * 4)
#define SMEM_TOTAL  (2 * 32 * BS_STRIDE * 4)   // 18432 B

__device__ __forceinline__ uint32_t pack_bf2(float a, float b) {
    __nv_bfloat162 h = __floats2bfloat162_rn(a, b);  // .x -> low 16 bits
    uint32_t u; memcpy(&u, &h, 4);
    return u;
}

__device__ __forceinline__ void split_pair(float xa, float xb,
                                           uint32_t& hi, uint32_t& lo) {
    hi = pack_bf2(xa, xb);
    __nv_bfloat162 hv; memcpy(&hv, &hi, 4);
    lo = pack_bf2(xa - __bfloat162float(hv.x), xb - __bfloat162float(hv.y));
}

#define MMA_BF16(d, a0, a1, a2, a3, b0, b1) \
    asm volatile("mma.sync.aligned.m16n8k16.row.col.f32.bf16.bf16.f32 " \
        "{%0,%1,%2,%3}, {%4,%5,%6,%7}, {%8,%9}, {%0,%1,%2,%3};" \
        : "+f"((d)[0]), "+f"((d)[1]), "+f"((d)[2]), "+f"((d)[3]) \
        : "r"(a0), "r"(a1), "r"(a2), "r"(a3), "r"(b0), "r"(b1))

__global__ __launch_bounds__(THREADS, 3)
void embed_mma_kernel(const float* __restrict__ in,
                      const float* __restrict__ emb,
                      float* __restrict__ out)
{
    extern __shared__ char smem[];
    uint32_t* Bh = reinterpret_cast<uint32_t*>(smem + SMEM_BH_OFF);
    uint32_t* Bl = reinterpret_cast<uint32_t*>(smem + SMEM_BL_OFF);

    const int t = threadIdx.x;
    const int b     = blockIdx.x >> 5;      // 32 s-tiles per batch
    const int stile = blockIdx.x & 31;
    const int s0    = stile * MTILE;

    // ---- stage B: read emb f32, split hi/lo, pack k-pairs ----
    // Bp[k2][e] = pack(emb[2k2][e], emb[2k2+1][e]); 32 x 64 u32 per array.
    {
        #pragma unroll
        for (int j = 0; j < 8; ++j) {
            int idx = j * THREADS + t;      // 0..2047
            int k2 = idx >> 6, e = idx & 63;
            float x0 = emb[(2 * k2) * ESZ + e];
            float x1 = emb[(2 * k2 + 1) * ESZ + e];
            uint32_t hp, lp;
            split_pair(x0, x1, hp, lp);
            Bh[k2 * BS_STRIDE + e] = hp;
            Bl[k2 * BS_STRIDE + e] = lp;
        }
    }
    __syncthreads();

    const int w    = t >> 5;
    const int lane = t & 31;
    const int r  = lane >> 2;     // 0..7
    const int cq = lane & 3;      // 0..3

    // warp covers s rows [s0+16w, s0+16w+16)
    const float* Ab = in + (size_t)b * (ISZ * SEQ) + s0 + 16 * w + r;

    float acc[8][4];
    #pragma unroll
    for (int nt = 0; nt < 8; ++nt)
        #pragma unroll
        for (int q = 0; q < 4; ++q) acc[nt][q] = 0.0f;

    #pragma unroll
    for (int ks = 0; ks < 4; ++ks) {
        const int ka = ks * 16 + 2 * cq;
        const float* P0 = Ab + (size_t)(ka    ) * SEQ;
        const float* P1 = Ab + (size_t)(ka + 1) * SEQ;
        const float* P8 = Ab + (size_t)(ka + 8) * SEQ;
        const float* P9 = Ab + (size_t)(ka + 9) * SEQ;

        const float v0l = P0[0], v1l = P1[0], v0h = P0[8], v1h = P1[8];
        const float v8l = P8[0], v9l = P9[0], v8h = P8[8], v9h = P9[8];

        uint32_t a0h, a1h, a2h, a3h, a0l, a1l, a2l, a3l;
        split_pair(v0l, v1l, a0h, a0l);
        split_pair(v0h, v1h, a1h, a1l);
        split_pair(v8l, v9l, a2h, a2l);
        split_pair(v8h, v9h, a3h, a3l);

        const uint32_t* bh0 = Bh + (ks * 8 + cq) * BS_STRIDE + r;
        const uint32_t* bh1 = Bh + (ks * 8 + cq + 4) * BS_STRIDE + r;
        const uint32_t* bl0 = Bl + (ks * 8 + cq) * BS_STRIDE + r;
        const uint32_t* bl1 = Bl + (ks * 8 + cq + 4) * BS_STRIDE + r;

        #pragma unroll
        for (int nt = 0; nt < 8; ++nt) {
            const uint32_t b0h = bh0[nt * 8];
            const uint32_t b1h = bh1[nt * 8];
            const uint32_t b0l = bl0[nt * 8];
            const uint32_t b1l = bl1[nt * 8];
            MMA_BF16(acc[nt], a0h, a1h, a2h, a3h, b0h, b1h);
            MMA_BF16(acc[nt], a0h, a1h, a2h, a3h, b0l, b1l);
            MMA_BF16(acc[nt], a0l, a1l, a2l, a3l, b0h, b1h);
        }
    }

    // ---- epilogue: c0,c1 -> row sl ; c2,c3 -> row sl+8 ----
    const size_t srow = (size_t)b * SEQ + s0 + 16 * w + r;
    float* orow  = out + srow * ESZ;
    float* orow8 = out + (srow + 8) * ESZ;
    #pragma unroll
    for (int nt = 0; nt < 8; ++nt) {
        *reinterpret_cast<float2*>(orow  + nt * 8 + 2 * cq) =
            make_float2(acc[nt][0], acc[nt][1]);
        *reinterpret_cast<float2*>(orow8 + nt * 8 + 2 * cq) =
            make_float2(acc[nt][2], acc[nt][3]);
    }
}

extern "C" void kernel_launch(void* const* d_in, const int* in_sizes, int n_in,
                              void* d_out, int out_size)
{
    const float* in  = (const float*)d_in[0];   // [64, 64, 4096]
    const float* emb = (const float*)d_in[1];   // [64, 64]
    float* out = (float*)d_out;                 // [64, 4096, 64]

    const int blocks = BATCH * (SEQ / MTILE);   // 64 * 32 = 2048
    embed_mma_kernel<<<blocks, THREADS, SMEM_TOTAL>>>(in, emb, out);
}

// round 8
// speedup vs baseline: 1.0169x; 1.0169x over previous
#include <cuda_runtime.h>
#include <cuda_bf16.h>
#include <cstdint>
#include <cstring>

// einsum('bis,ie->bse') via mma.sync bf16 3-term split.
//   inputs    [B=64, I=64, S=4096] f32
//   embedding [I=64, E=64]         f32
//   out       [B=64, S=4096, E=64] f32
//
// D = Ahi*Bhi + Ahi*Blo + Alo*Bhi  (bf16 operands, fp32 accumulate)
// rel err ~3.4e-6 (validated).
//
// vs round 6: occupancy play. mt=1 (32-reg accumulator) + launch_bounds(256,3)
// -> 24 warps/SM instead of 16. All pipes had >=40% headroom and issue was 22%,
// so the kernel was latency-bound on too few warps; extra B-fragment LDS
// traffic (L1 61% -> ~73%) is the accepted cost.

#define BATCH 64
#define ISZ   64
#define SEQ   4096
#define ESZ   64
#define MTILE 128        // s per CTA
#define THREADS 256

#define BS_STRIDE 72     // u32 words per k2-row; conflict-free fragment reads
#define SMEM_BH_OFF 0
#define SMEM_BL_OFF (32 * BS_STRIDE * 4)
#define SMEM_TOTAL  (2 * 32 * BS_STRIDE * 4)   // 18432 B

__device__ __forceinline__ uint32_t pack_bf2(float a, float b) {
    __nv_bfloat162 h = __floats2bfloat162_rn(a, b);  // .x -> low 16 bits
    uint32_t u; memcpy(&u, &h, 4);
    return u;
}

__device__ __forceinline__ void split_pair(float xa, float xb,
                                           uint32_t& hi, uint32_t& lo) {
    hi = pack_bf2(xa, xb);
    __nv_bfloat162 hv; memcpy(&hv, &hi, 4);
    lo = pack_bf2(xa - __bfloat162float(hv.x), xb - __bfloat162float(hv.y));
}

#define MMA_BF16(d, a0, a1, a2, a3, b0, b1) \
    asm volatile("mma.sync.aligned.m16n8k16.row.col.f32.bf16.bf16.f32 " \
        "{%0,%1,%2,%3}, {%4,%5,%6,%7}, {%8,%9}, {%0,%1,%2,%3};" \
        : "+f"((d)[0]), "+f"((d)[1]), "+f"((d)[2]), "+f"((d)[3]) \
        : "r"(a0), "r"(a1), "r"(a2), "r"(a3), "r"(b0), "r"(b1))

__global__ __launch_bounds__(THREADS, 3)
void embed_mma_kernel(const float* __restrict__ in,
                      const float* __restrict__ emb,
                      float* __restrict__ out)
{
    extern __shared__ char smem[];
    uint32_t* Bh = reinterpret_cast<uint32_t*>(smem + SMEM_BH_OFF);
    uint32_t* Bl = reinterpret_cast<uint32_t*>(smem + SMEM_BL_OFF);

    const int t = threadIdx.x;
    const int b     = blockIdx.x >> 5;      // 32 s-tiles per batch
    const int stile = blockIdx.x & 31;
    const int s0    = stile * MTILE;

    // ---- stage B: read emb f32, split hi/lo, pack k-pairs ----
    // Bp[k2][e] = pack(emb[2k2][e], emb[2k2+1][e]); 32 x 64 u32 per array.
    {
        #pragma unroll
        for (int j = 0; j < 8; ++j) {
            int idx = j * THREADS + t;      // 0..2047
            int k2 = idx >> 6, e = idx & 63;
            float x0 = emb[(2 * k2) * ESZ + e];
            float x1 = emb[(2 * k2 + 1) * ESZ + e];
            uint32_t hp, lp;
            split_pair(x0, x1, hp, lp);
            Bh[k2 * BS_STRIDE + e] = hp;
            Bl[k2 * BS_STRIDE + e] = lp;
        }
    }
    __syncthreads();

    const int w    = t >> 5;
    const int lane = t & 31;
    const int r  = lane >> 2;     // 0..7
    const int cq = lane & 3;      // 0..3

    // warp covers s rows [s0+16w, s0+16w+16)
    const float* Ab = in + (size_t)b * (ISZ * SEQ) + s0 + 16 * w + r;

    float acc[8][4];
    #pragma unroll
    for (int nt = 0; nt < 8; ++nt)
        #pragma unroll
        for (int q = 0; q < 4; ++q) acc[nt][q] = 0.0f;

    #pragma unroll
    for (int ks = 0; ks < 4; ++ks) {
        const int ka = ks * 16 + 2 * cq;
        const float* P0 = Ab + (size_t)(ka    ) * SEQ;
        const float* P1 = Ab + (size_t)(ka + 1) * SEQ;
        const float* P8 = Ab + (size_t)(ka + 8) * SEQ;
        const float* P9 = Ab + (size_t)(ka + 9) * SEQ;

        const float v0l = P0[0], v1l = P1[0], v0h = P0[8], v1h = P1[8];
        const float v8l = P8[0], v9l = P9[0], v8h = P8[8], v9h = P9[8];

        uint32_t a0h, a1h, a2h, a3h, a0l, a1l, a2l, a3l;
        split_pair(v0l, v1l, a0h, a0l);
        split_pair(v0h, v1h, a1h, a1l);
        split_pair(v8l, v9l, a2h, a2l);
        split_pair(v8h, v9h, a3h, a3l);

        const uint32_t* bh0 = Bh + (ks * 8 + cq) * BS_STRIDE + r;
        const uint32_t* bh1 = Bh + (ks * 8 + cq + 4) * BS_STRIDE + r;
        const uint32_t* bl0 = Bl + (ks * 8 + cq) * BS_STRIDE + r;
        const uint32_t* bl1 = Bl + (ks * 8 + cq + 4) * BS_STRIDE + r;

        #pragma unroll
        for (int nt = 0; nt < 8; ++nt) {
            const uint32_t b0h = bh0[nt * 8];
            const uint32_t b1h = bh1[nt * 8];
            const uint32_t b0l = bl0[nt * 8];
            const uint32_t b1l = bl1[nt * 8];
            MMA_BF16(acc[nt], a0h, a1h, a2h, a3h, b0h, b1h);
            MMA_BF16(acc[nt], a0h, a1h, a2h, a3h, b0l, b1l);
            MMA_BF16(acc[nt], a0l, a1l, a2l, a3l, b0h, b1h);
        }
    }

    // ---- epilogue: c0,c1 -> row sl ; c2,c3 -> row sl+8 ----
    const size_t srow = (size_t)b * SEQ + s0 + 16 * w + r;
    float* orow  = out + srow * ESZ;
    float* orow8 = out + (srow + 8) * ESZ;
    #pragma unroll
    for (int nt = 0; nt < 8; ++nt) {
        *reinterpret_cast<float2*>(orow  + nt * 8 + 2 * cq) =
            make_float2(acc[nt][0], acc[nt][1]);
        *reinterpret_cast<float2*>(orow8 + nt * 8 + 2 * cq) =
            make_float2(acc[nt][2], acc[nt][3]);
    }
}

extern "C" void kernel_launch(void* const* d_in, const int* in_sizes, int n_in,
                              void* d_out, int out_size)
{
    const float* in  = (const float*)d_in[0];   // [64, 64, 4096]
    const float* emb = (const float*)d_in[1];   // [64, 64]
    float* out = (float*)d_out;                 // [64, 4096, 64]

    const int blocks = BATCH * (SEQ / MTILE);   // 64 * 32 = 2048
    embed_mma_kernel<<<blocks, THREADS, SMEM_TOTAL>>>(in, emb, out);
}

// round 9
// speedup vs baseline: 1.0723x; 1.0545x over previous
#include <cuda_runtime.h>
#include <cuda_bf16.h>
#include <cstdint>
#include <cstring>

// einsum('bis,ie->bse') via mma.sync bf16 3-term split.
//   inputs    [B=64, I=64, S=4096] f32
//   embedding [I=64, E=64]         f32
//   out       [B=64, S=4096, E=64] f32
//
// D = Ahi*Bhi + Ahi*Blo + Alo*Bhi  (bf16, fp32 accumulate), rel err ~3.4e-6.
//
// vs round 6 (best, mt=2): A tile staged through shared memory. The mainloop
// had 16 scattered LDGs per ks whose ~300-600cyc latency 16 warps could not
// hide (issue 22%, nothing saturated). Staging pays LDG latency once per CTA
// at MLP~16, turns mainloop memory ops into 29cyc conflict-free LDS, and cuts
// L1 wavefronts (4-sector scattered LDG -> 1-wf LDS).

#define BATCH 64
#define ISZ   64
#define SEQ   4096
#define ESZ   64
#define MTILE 256        // s per CTA
#define THREADS 256

#define AS_STRIDE 260    // f32 words per k-row: bank = 4k + s (mod 32) -> frag reads conflict-free
#define BS_STRIDE 72     // u32 words per k2-row
#define SMEM_A_BYTES  (64 * AS_STRIDE * 4)              // 66560
#define SMEM_BH_OFF   SMEM_A_BYTES
#define SMEM_BL_OFF   (SMEM_A_BYTES + 32 * BS_STRIDE * 4)
#define SMEM_TOTAL    (SMEM_A_BYTES + 2 * 32 * BS_STRIDE * 4)   // 84992 B

__device__ __forceinline__ uint32_t pack_bf2(float a, float b) {
    __nv_bfloat162 h = __floats2bfloat162_rn(a, b);  // .x -> low 16 bits
    uint32_t u; memcpy(&u, &h, 4);
    return u;
}

__device__ __forceinline__ void split_pair(float xa, float xb,
                                           uint32_t& hi, uint32_t& lo) {
    hi = pack_bf2(xa, xb);
    __nv_bfloat162 hv; memcpy(&hv, &hi, 4);
    lo = pack_bf2(xa - __bfloat162float(hv.x), xb - __bfloat162float(hv.y));
}

#define MMA_BF16(d, a0, a1, a2, a3, b0, b1) \
    asm volatile("mma.sync.aligned.m16n8k16.row.col.f32.bf16.bf16.f32 " \
        "{%0,%1,%2,%3}, {%4,%5,%6,%7}, {%8,%9}, {%0,%1,%2,%3};" \
        : "+f"((d)[0]), "+f"((d)[1]), "+f"((d)[2]), "+f"((d)[3]) \
        : "r"(a0), "r"(a1), "r"(a2), "r"(a3), "r"(b0), "r"(b1))

__global__ __launch_bounds__(THREADS, 2)
void embed_mma_kernel(const float* __restrict__ in,
                      const float* __restrict__ emb,
                      float* __restrict__ out)
{
    extern __shared__ char smem[];
    float*    As = reinterpret_cast<float*>(smem);
    uint32_t* Bh = reinterpret_cast<uint32_t*>(smem + SMEM_BH_OFF);
    uint32_t* Bl = reinterpret_cast<uint32_t*>(smem + SMEM_BL_OFF);

    const int t = threadIdx.x;
    const int b     = blockIdx.x >> 4;      // 16 s-tiles per batch
    const int stile = blockIdx.x & 15;
    const int s0    = stile * MTILE;

    // ---- stage A tile [64k][256s] f32: coalesced LDG.128 at MLP 16 ----
    {
        const float4* gin = reinterpret_cast<const float4*>(
            in + (size_t)b * (ISZ * SEQ) + s0);
        #pragma unroll
        for (int j = 0; j < 16; ++j) {
            int u  = j * THREADS + t;       // 0..4095 float4 units
            int k  = u >> 6;                // 0..63
            int s4 = u & 63;                // float4 index within 256-s row
            float4 v = gin[(size_t)k * (SEQ / 4) + s4];
            *reinterpret_cast<float4*>(As + k * AS_STRIDE + 4 * s4) = v;
        }
    }
    // ---- stage B: split hi/lo, pack k-pairs: Bp[k2][e] ----
    {
        #pragma unroll
        for (int j = 0; j < 8; ++j) {
            int idx = j * THREADS + t;      // 0..2047
            int k2 = idx >> 6, e = idx & 63;
            float x0 = emb[(2 * k2) * ESZ + e];
            float x1 = emb[(2 * k2 + 1) * ESZ + e];
            uint32_t hp, lp;
            split_pair(x0, x1, hp, lp);
            Bh[k2 * BS_STRIDE + e] = hp;
            Bl[k2 * BS_STRIDE + e] = lp;
        }
    }
    __syncthreads();

    const int w    = t >> 5;
    const int lane = t & 31;
    const int r  = lane >> 2;     // 0..7
    const int cq = lane & 3;      // 0..3

    // warp covers s in [32w, 32w+32): m-tile 0 rows r/r+8, m-tile 1 at +16/+24
    const int sbase = 32 * w + r;

    float acc[2][8][4];
    #pragma unroll
    for (int mt = 0; mt < 2; ++mt)
        #pragma unroll
        for (int nt = 0; nt < 8; ++nt)
            #pragma unroll
            for (int q = 0; q < 4; ++q) acc[mt][nt][q] = 0.0f;

    #pragma unroll
    for (int ks = 0; ks < 4; ++ks) {
        const int ka = ks * 16 + 2 * cq;
        const float* P0 = As + (ka    ) * AS_STRIDE + sbase;
        const float* P1 = As + (ka + 1) * AS_STRIDE + sbase;
        const float* P8 = As + (ka + 8) * AS_STRIDE + sbase;
        const float* P9 = As + (ka + 9) * AS_STRIDE + sbase;

        // A values from smem (conflict-free LDS), both m-tiles
        const float v00 = P0[0],  v10 = P1[0],  v08 = P0[8],  v18 = P1[8];
        const float v80 = P8[0],  v90 = P9[0],  v88 = P8[8],  v98 = P9[8];
        const float u00 = P0[16], u10 = P1[16], u08 = P0[24], u18 = P1[24];
        const float u80 = P8[16], u90 = P9[16], u88 = P8[24], u98 = P9[24];

        uint32_t a0h[2], a1h[2], a2h[2], a3h[2];
        uint32_t a0l[2], a1l[2], a2l[2], a3l[2];
        split_pair(v00, v10, a0h[0], a0l[0]);
        split_pair(v08, v18, a1h[0], a1l[0]);
        split_pair(v80, v90, a2h[0], a2l[0]);
        split_pair(v88, v98, a3h[0], a3l[0]);
        split_pair(u00, u10, a0h[1], a0l[1]);
        split_pair(u08, u18, a1h[1], a1l[1]);
        split_pair(u80, u90, a2h[1], a2l[1]);
        split_pair(u88, u98, a3h[1], a3l[1]);

        const uint32_t* bh0 = Bh + (ks * 8 + cq) * BS_STRIDE + r;
        const uint32_t* bh1 = Bh + (ks * 8 + cq + 4) * BS_STRIDE + r;
        const uint32_t* bl0 = Bl + (ks * 8 + cq) * BS_STRIDE + r;
        const uint32_t* bl1 = Bl + (ks * 8 + cq + 4) * BS_STRIDE + r;

        uint32_t B0h[8], B1h[8], B0l[8], B1l[8];
        #pragma unroll
        for (int nt = 0; nt < 8; ++nt) {
            B0h[nt] = bh0[nt * 8];
            B1h[nt] = bh1[nt * 8];
            B0l[nt] = bl0[nt * 8];
            B1l[nt] = bl1[nt * 8];
        }

        #pragma unroll
        for (int nt = 0; nt < 8; ++nt) {
            MMA_BF16(acc[0][nt], a0h[0], a1h[0], a2h[0], a3h[0], B0h[nt], B1h[nt]);
            MMA_BF16(acc[0][nt], a0h[0], a1h[0], a2h[0], a3h[0], B0l[nt], B1l[nt]);
            MMA_BF16(acc[0][nt], a0l[0], a1l[0], a2l[0], a3l[0], B0h[nt], B1h[nt]);
            MMA_BF16(acc[1][nt], a0h[1], a1h[1], a2h[1], a3h[1], B0h[nt], B1h[nt]);
            MMA_BF16(acc[1][nt], a0h[1], a1h[1], a2h[1], a3h[1], B0l[nt], B1l[nt]);
            MMA_BF16(acc[1][nt], a0l[1], a1l[1], a2l[1], a3l[1], B0h[nt], B1h[nt]);
        }
    }

    // ---- epilogue: c0,c1 -> row s ; c2,c3 -> row s+8 ----
    #pragma unroll
    for (int mt = 0; mt < 2; ++mt) {
        const size_t srow = (size_t)b * SEQ + s0 + sbase + 16 * mt;
        float* orow  = out + srow * ESZ;
        float* orow8 = out + (srow + 8) * ESZ;
        #pragma unroll
        for (int nt = 0; nt < 8; ++nt) {
            *reinterpret_cast<float2*>(orow  + nt * 8 + 2 * cq) =
                make_float2(acc[mt][nt][0], acc[mt][nt][1]);
            *reinterpret_cast<float2*>(orow8 + nt * 8 + 2 * cq) =
                make_float2(acc[mt][nt][2], acc[mt][nt][3]);
        }
    }
}

extern "C" void kernel_launch(void* const* d_in, const int* in_sizes, int n_in,
                              void* d_out, int out_size)
{
    const float* in  = (const float*)d_in[0];   // [64, 64, 4096]
    const float* emb = (const float*)d_in[1];   // [64, 64]
    float* out = (float*)d_out;                 // [64, 4096, 64]

    cudaFuncSetAttribute(embed_mma_kernel,
                         cudaFuncAttributeMaxDynamicSharedMemorySize, SMEM_TOTAL);

    const int blocks = BATCH * (SEQ / MTILE);   // 64 * 16 = 1024
    embed_mma_kernel<<<blocks, THREADS, SMEM_TOTAL>>>(in, emb, out);
}